// round 3
// baseline (speedup 1.0000x reference)
#include <cuda_runtime.h>

// Fully-coalesced single-pass reduction with front-batched loads (MLP ~17).
// Fast path (full 256-row block): every thread issues all its ~17 LDG.128
// back-to-back into registers before touching smem. Slow generic path only
// for the final partial block.

#define RPB 256
#define MU_PRIOR  0.6447f
#define LOGDET_SA 4.76770561517f   // 3*log(4.9)
#define INV49     (1.0f/4.9f)

#define W0 (1.0f/(0.0015f *0.0015f ))
#define W1 (1.0f/(0.0012f *0.0012f ))
#define W2 (1.0f/(0.001f  *0.001f  ))
#define W3 (1.0f/(0.00086f*0.00086f))
#define W4 (1.0f/(0.00057f*0.00057f))

__constant__ float c_W5[5] = {W0, W1, W2, W3, W4};
// c_W20[p*4+c] = W[(p+c)%5]
__constant__ float c_W20[20] = {
    W0, W1, W2, W3,
    W1, W2, W3, W4,
    W2, W3, W4, W0,
    W3, W4, W0, W1,
    W4, W0, W1, W2
};

__device__ float    g_partial = 0.f;
__device__ unsigned g_count   = 0u;

__device__ __forceinline__ float wssq(float4 a, float4 b, int p) {
    const float* w = &c_W20[p * 4];
    float acc, d;
    d = a.x - b.x; acc  = w[0] * d * d;
    d = a.y - b.y; acc += w[1] * d * d;
    d = a.z - b.z; acc += w[2] * d * d;
    d = a.w - b.w; acc += w[3] * d * d;
    return acc;
}

__global__ void __launch_bounds__(256, 2)
loss_kernel(const float4* __restrict__ pred4, const float4* __restrict__ yobs4,
            const float4* __restrict__ rrs4,  const float4* __restrict__ rrsp4,
            const float4* __restrict__ nan4,  const float4* __restrict__ cov4,
            const float4* __restrict__ mu4,   const float*  __restrict__ prm,
            float* __restrict__ out,
            int n, int nblocks, int np,
            float s_rrs, float s_obs, float s_dk, float s_mu)
{
    __shared__ __align__(16) float s_dy2[RPB * 9];
    __shared__ __align__(16) float s_fin[RPB * 9];
    __shared__ __align__(16) float s_cov[RPB * 9];
    __shared__ float wsum[8];

    const int tid  = threadIdx.x;
    const int b    = blockIdx.x;
    const int row0 = b * RPB;
    const int rows = min(RPB, n - row0);

    float tot = 0.f;

    if (rows == RPB) {
        // ================= FAST PATH: full block =================
        const float4* p4 = pred4 + row0 * 9 / 4;   // 576*b
        const float4* q4 = yobs4 + row0 * 9 / 4;
        const float4* z4 = nan4  + row0 * 9 / 4;
        const float4* c4 = cov4  + row0 * 9 / 4;
        const float4* a4 = rrs4  + row0 * 5 / 4;   // 320*b
        const float4* e4 = rrsp4 + row0 * 5 / 4;
        const float4* m4 = mu4   + row0 * 3 / 4;   // 192*b

        const bool t3 = tid < 64;    // third 9-wide batch (576 = 2*256 + 64)
        const bool t5 = tid < 64;    // second rrs batch   (320 = 256 + 64)
        const bool tm = tid < 192;   // mu batch           (192)
        const float4 zero4 = make_float4(0.f, 0.f, 0.f, 0.f);
        const float4 mu0   = make_float4(MU_PRIOR, MU_PRIOR, MU_PRIOR, MU_PRIOR);

        // ---- front-batched loads (17 LDG.128) ----
        float4 P0 = p4[tid];       float4 P1 = p4[tid + 256];
        float4 Q0 = q4[tid];       float4 Q1 = q4[tid + 256];
        float4 Z0 = z4[tid];       float4 Z1 = z4[tid + 256];
        float4 C0 = c4[tid];       float4 C1 = c4[tid + 256];
        float4 P2 = t3 ? p4[tid + 512] : zero4;
        float4 Q2 = t3 ? q4[tid + 512] : zero4;
        float4 Z2 = t3 ? z4[tid + 512] : zero4;
        float4 C2 = t3 ? c4[tid + 512] : zero4;
        float4 A0 = a4[tid];       float4 E0 = e4[tid];
        float4 A1 = t5 ? a4[tid + 256] : zero4;
        float4 E1 = t5 ? e4[tid + 256] : zero4;
        float4 M0 = tm ? m4[tid] : mu0;

        // ---- rrs weighted SSQ (zero diff for inactive -> no predicate) ----
        {
            int p0 = (int)((unsigned)(4 * tid) % 5u);
            int p1 = (int)((unsigned)(4 * tid + 4) % 5u);   // +1024 == +4 (mod 5)
            tot += (wssq(A0, E0, p0) + wssq(A1, E1, p1)) * s_rrs;
        }

        // ---- mu SSQ (inactive lanes loaded MU_PRIOR -> zero) ----
        {
            float acc, d;
            d = M0.x - MU_PRIOR; acc  = d * d;
            d = M0.y - MU_PRIOR; acc += d * d;
            d = M0.z - MU_PRIOR; acc += d * d;
            d = M0.w - MU_PRIOR; acc += d * d;
            tot += acc * s_mu;
        }

        // ---- stage dy^2 / finite-flags / cov into smem ----
        float4* sd4 = reinterpret_cast<float4*>(s_dy2);
        float4* sf4 = reinterpret_cast<float4*>(s_fin);
        float4* sc4 = reinterpret_cast<float4*>(s_cov);
        {
            float4 dsq, fin; float d;
            d = P0.x - Q0.x; dsq.x = d * d; fin.x = (Z0.x == Z0.x) ? 1.f : 0.f;
            d = P0.y - Q0.y; dsq.y = d * d; fin.y = (Z0.y == Z0.y) ? 1.f : 0.f;
            d = P0.z - Q0.z; dsq.z = d * d; fin.z = (Z0.z == Z0.z) ? 1.f : 0.f;
            d = P0.w - Q0.w; dsq.w = d * d; fin.w = (Z0.w == Z0.w) ? 1.f : 0.f;
            sd4[tid] = dsq; sf4[tid] = fin; sc4[tid] = C0;

            d = P1.x - Q1.x; dsq.x = d * d; fin.x = (Z1.x == Z1.x) ? 1.f : 0.f;
            d = P1.y - Q1.y; dsq.y = d * d; fin.y = (Z1.y == Z1.y) ? 1.f : 0.f;
            d = P1.z - Q1.z; dsq.z = d * d; fin.z = (Z1.z == Z1.z) ? 1.f : 0.f;
            d = P1.w - Q1.w; dsq.w = d * d; fin.w = (Z1.w == Z1.w) ? 1.f : 0.f;
            sd4[tid + 256] = dsq; sf4[tid + 256] = fin; sc4[tid + 256] = C1;

            if (t3) {
                d = P2.x - Q2.x; dsq.x = d * d; fin.x = (Z2.x == Z2.x) ? 1.f : 0.f;
                d = P2.y - Q2.y; dsq.y = d * d; fin.y = (Z2.y == Z2.y) ? 1.f : 0.f;
                d = P2.z - Q2.z; dsq.z = d * d; fin.z = (Z2.z == Z2.z) ? 1.f : 0.f;
                d = P2.w - Q2.w; dsq.w = d * d; fin.w = (Z2.w == Z2.w) ? 1.f : 0.f;
                sd4[tid + 512] = dsq; sf4[tid + 512] = fin; sc4[tid + 512] = C2;
            }
        }
        __syncthreads();

        // ---- per-row math (1 row per thread, stride-9 smem = conflict-free) ----
        {
            const float* dy = &s_dy2[tid * 9];
            const float* fi = &s_fin[tid * 9];
            const float* cm = &s_cov[tid * 9];

            float rsum = 0.f, lens = 0.f;
            #pragma unroll
            for (int i = 0; i < 9; i++) { rsum += dy[i]; lens += fi[i]; }
            tot += __fdividef(rsum, lens) * s_obs;

            float m0 = cm[0], m1 = cm[1], m2 = cm[2];
            float m3 = cm[3], m4 = cm[4], m5 = cm[5];
            float m6 = cm[6], m7 = cm[7], m8 = cm[8];
            float tr  = m0 + m4 + m8;
            float det = m0 * (m4 * m8 - m5 * m7)
                      - m1 * (m3 * m8 - m5 * m6)
                      + m2 * (m3 * m7 - m4 * m6);
            tot += ((LOGDET_SA - __logf(det)) + tr * INV49) * s_dk;
        }
    } else {
        // ================= SLOW PATH: final partial block =================
        {
            const int base = row0 * 5;
            const int nf   = rows * 5;
            const float* af = (const float*)rrs4;
            const float* ef = (const float*)rrsp4;
            float acc = 0.f;
            for (int g = base + tid; g < base + nf; g += 256) {
                float d = af[g] - ef[g];
                acc += c_W5[(unsigned)g % 5u] * d * d;
            }
            tot += acc * s_rrs;
        }
        {
            const int base = row0 * 3;
            const int nf   = rows * 3;
            const float* mf = (const float*)mu4;
            float acc = 0.f;
            for (int g = base + tid; g < base + nf; g += 256) {
                float d = mf[g] - MU_PRIOR;
                acc += d * d;
            }
            tot += acc * s_mu;
        }
        {
            const int base = row0 * 9;
            const int nf   = rows * 9;
            const float* pf = (const float*)pred4;
            const float* qf = (const float*)yobs4;
            const float* zf = (const float*)nan4;
            const float* cf = (const float*)cov4;
            for (int j = tid; j < nf; j += 256) {
                float d = pf[base + j] - qf[base + j];
                s_dy2[j] = d * d;
                float z = zf[base + j];
                s_fin[j] = (z == z) ? 1.f : 0.f;
                s_cov[j] = cf[base + j];
            }
        }
        __syncthreads();
        for (int r = tid; r < rows; r += 256) {
            const float* dy = &s_dy2[r * 9];
            const float* fi = &s_fin[r * 9];
            const float* cm = &s_cov[r * 9];
            float rsum = 0.f, lens = 0.f;
            #pragma unroll
            for (int i = 0; i < 9; i++) { rsum += dy[i]; lens += fi[i]; }
            tot += __fdividef(rsum, lens) * s_obs;
            float m0 = cm[0], m1 = cm[1], m2 = cm[2];
            float m3 = cm[3], m4 = cm[4], m5 = cm[5];
            float m6 = cm[6], m7 = cm[7], m8 = cm[8];
            float tr  = m0 + m4 + m8;
            float det = m0 * (m4 * m8 - m5 * m7)
                      - m1 * (m3 * m8 - m5 * m6)
                      + m2 * (m3 * m7 - m4 * m6);
            tot += ((LOGDET_SA - __logf(det)) + tr * INV49) * s_dk;
        }
    }

    // ---- params l2 (block 0 only) ----
    if (b == 0) {
        float acc = 0.f;
        for (int i = tid; i < np; i += 256) {
            float d = prm[i] - 1.f;
            acc += d * d;
        }
        tot += acc / (float)np;
    }

    // ---- block reduction + grid finalize ----
    #pragma unroll
    for (int o = 16; o > 0; o >>= 1) tot += __shfl_down_sync(0xffffffffu, tot, o);
    int lane = tid & 31;
    int wid  = tid >> 5;
    if (lane == 0) wsum[wid] = tot;
    __syncthreads();
    if (wid == 0) {
        float v = (lane < 8) ? wsum[lane] : 0.f;
        #pragma unroll
        for (int o = 4; o > 0; o >>= 1) v += __shfl_down_sync(0xffffffffu, v, o);
        if (lane == 0) {
            atomicAdd(&g_partial, v);
            __threadfence();
            unsigned c = atomicAdd(&g_count, 1u);
            if (c == (unsigned)(nblocks - 1)) {
                __threadfence();
                float total = atomicExch(&g_partial, 0.f);  // read + reset for replay
                out[0] = total;
                g_count = 0u;
            }
        }
    }
}

extern "C" void kernel_launch(void* const* d_in, const int* in_sizes, int n_in,
                              void* d_out, int out_size)
{
    const float4* pred = (const float4*)d_in[0];
    const float4* yobs = (const float4*)d_in[1];
    const float4* rrs  = (const float4*)d_in[2];
    const float4* rrsp = (const float4*)d_in[3];
    const float4* nana = (const float4*)d_in[4];
    const float4* cov  = (const float4*)d_in[5];
    const float4* mu   = (const float4*)d_in[6];
    const float*  prm  = (const float*)d_in[7];
    float* out = (float*)d_out;

    int n  = in_sizes[0] / 9;
    int np = in_sizes[7];
    int nblocks = (n + RPB - 1) / RPB;

    double dn = (double)n;
    float s_rrs = (float)(1.0 / (5.0 * dn));
    float s_obs = (float)(10.0 / dn);
    float s_dk  = (float)(0.5 / dn);
    float s_mu  = (float)(0.5 / (4.9 * 3.0 * dn));

    loss_kernel<<<nblocks, 256>>>(pred, yobs, rrs, rrsp, nana, cov, mu, prm,
                                  out, n, nblocks, np,
                                  s_rrs, s_obs, s_dk, s_mu);
}

// round 4
// speedup vs baseline: 1.1623x; 1.1623x over previous
#include <cuda_runtime.h>

// Coalesced single-pass reduction. Staging loop double-unrolled with an
// 8-deep LDG.128 front batch (moderate MLP), __ldcs streaming hints
// everywhere (read-once data), regs capped for 5 CTAs/SM.

#define RPB 256
#define MU_PRIOR  0.6447f
#define LOGDET_SA 4.76770561517f   // 3*log(4.9)
#define INV49     (1.0f/4.9f)

#define W0 (1.0f/(0.0015f *0.0015f ))
#define W1 (1.0f/(0.0012f *0.0012f ))
#define W2 (1.0f/(0.001f  *0.001f  ))
#define W3 (1.0f/(0.00086f*0.00086f))
#define W4 (1.0f/(0.00057f*0.00057f))

__constant__ float c_W5[5] = {W0, W1, W2, W3, W4};
__constant__ float c_W20[20] = {
    W0, W1, W2, W3,
    W1, W2, W3, W4,
    W2, W3, W4, W0,
    W3, W4, W0, W1,
    W4, W0, W1, W2
};

__device__ float    g_partial = 0.f;
__device__ unsigned g_count   = 0u;

__device__ __forceinline__ float wssq(float4 a, float4 b, int p) {
    const float* w = &c_W20[p * 4];
    float acc, d;
    d = a.x - b.x; acc  = w[0] * d * d;
    d = a.y - b.y; acc += w[1] * d * d;
    d = a.z - b.z; acc += w[2] * d * d;
    d = a.w - b.w; acc += w[3] * d * d;
    return acc;
}

__device__ __forceinline__ void stage_one(float4 P, float4 Q, float4 Z, float4 C,
                                          float4* sd4, float4* sf4, float4* sc4, int idx) {
    float4 dsq, fin; float d;
    d = P.x - Q.x; dsq.x = d * d; fin.x = (Z.x == Z.x) ? 1.f : 0.f;
    d = P.y - Q.y; dsq.y = d * d; fin.y = (Z.y == Z.y) ? 1.f : 0.f;
    d = P.z - Q.z; dsq.z = d * d; fin.z = (Z.z == Z.z) ? 1.f : 0.f;
    d = P.w - Q.w; dsq.w = d * d; fin.w = (Z.w == Z.w) ? 1.f : 0.f;
    sd4[idx] = dsq; sf4[idx] = fin; sc4[idx] = C;
}

__global__ void __launch_bounds__(256, 5)
loss_kernel(const float4* __restrict__ pred4, const float4* __restrict__ yobs4,
            const float4* __restrict__ rrs4,  const float4* __restrict__ rrsp4,
            const float4* __restrict__ nan4,  const float4* __restrict__ cov4,
            const float4* __restrict__ mu4,   const float*  __restrict__ prm,
            float* __restrict__ out,
            int n, int nblocks, int np,
            float s_rrs, float s_obs, float s_dk, float s_mu)
{
    __shared__ __align__(16) float s_dy2[RPB * 9];
    __shared__ __align__(16) float s_fin[RPB * 9];
    __shared__ __align__(16) float s_cov[RPB * 9];
    __shared__ float wsum[8];

    const int tid  = threadIdx.x;
    const int b    = blockIdx.x;
    const int row0 = b * RPB;
    const int rows = min(RPB, n - row0);

    float4* sd4 = reinterpret_cast<float4*>(s_dy2);
    float4* sf4 = reinterpret_cast<float4*>(s_fin);
    float4* sc4 = reinterpret_cast<float4*>(s_cov);

    float tot = 0.f;

    if (rows == RPB) {
        // ================= FAST PATH: full 256-row tile =================
        const float4* p4 = pred4 + row0 * 9 / 4;   // base 576*b
        const float4* q4 = yobs4 + row0 * 9 / 4;
        const float4* z4 = nan4  + row0 * 9 / 4;
        const float4* c4 = cov4  + row0 * 9 / 4;
        const float4* a4 = rrs4  + row0 * 5 / 4;   // base 320*b
        const float4* e4 = rrsp4 + row0 * 5 / 4;
        const float4* m4 = mu4   + row0 * 3 / 4;   // base 192*b

        // ---- staging: 8-deep front batch (iterations tid, tid+256) ----
        float4 P0 = __ldcs(p4 + tid);       float4 P1 = __ldcs(p4 + tid + 256);
        float4 Q0 = __ldcs(q4 + tid);       float4 Q1 = __ldcs(q4 + tid + 256);
        float4 Z0 = __ldcs(z4 + tid);       float4 Z1 = __ldcs(z4 + tid + 256);
        float4 C0 = __ldcs(c4 + tid);       float4 C1 = __ldcs(c4 + tid + 256);
        stage_one(P0, Q0, Z0, C0, sd4, sf4, sc4, tid);
        stage_one(P1, Q1, Z1, C1, sd4, sf4, sc4, tid + 256);
        if (tid < 64) {
            float4 P2 = __ldcs(p4 + tid + 512);
            float4 Q2 = __ldcs(q4 + tid + 512);
            float4 Z2 = __ldcs(z4 + tid + 512);
            float4 C2 = __ldcs(c4 + tid + 512);
            stage_one(P2, Q2, Z2, C2, sd4, sf4, sc4, tid + 512);
        }

        // ---- flat rrs weighted SSQ ----
        {
            float4 A0 = __ldcs(a4 + tid);
            float4 E0 = __ldcs(e4 + tid);
            int p0 = (int)((unsigned)(4 * tid) % 5u);
            tot += wssq(A0, E0, p0) * s_rrs;
            if (tid < 64) {
                float4 A1 = __ldcs(a4 + tid + 256);
                float4 E1 = __ldcs(e4 + tid + 256);
                int p1 = (int)((unsigned)(4 * tid + 4) % 5u);  // +1024 ≡ +4 (mod 5)
                tot += wssq(A1, E1, p1) * s_rrs;
            }
        }

        // ---- flat mu SSQ ----
        if (tid < 192) {
            float4 M0 = __ldcs(m4 + tid);
            float acc, d;
            d = M0.x - MU_PRIOR; acc  = d * d;
            d = M0.y - MU_PRIOR; acc += d * d;
            d = M0.z - MU_PRIOR; acc += d * d;
            d = M0.w - MU_PRIOR; acc += d * d;
            tot += acc * s_mu;
        }

        __syncthreads();

        // ---- per-row math (1 row/thread, stride-9 smem = conflict-free) ----
        {
            const float* dy = &s_dy2[tid * 9];
            const float* fi = &s_fin[tid * 9];
            const float* cm = &s_cov[tid * 9];

            float rsum = 0.f, lens = 0.f;
            #pragma unroll
            for (int i = 0; i < 9; i++) { rsum += dy[i]; lens += fi[i]; }
            tot += __fdividef(rsum, lens) * s_obs;

            float m0 = cm[0], m1 = cm[1], m2 = cm[2];
            float m3 = cm[3], m4 = cm[4], m5 = cm[5];
            float m6 = cm[6], m7 = cm[7], m8 = cm[8];
            float tr  = m0 + m4 + m8;
            float det = m0 * (m4 * m8 - m5 * m7)
                      - m1 * (m3 * m8 - m5 * m6)
                      + m2 * (m3 * m7 - m4 * m6);
            tot += ((LOGDET_SA - __logf(det)) + tr * INV49) * s_dk;
        }
    } else {
        // ================= SLOW PATH: final partial tile =================
        {
            const int base = row0 * 5;
            const int nf   = rows * 5;
            const float* af = (const float*)rrs4;
            const float* ef = (const float*)rrsp4;
            float acc = 0.f;
            for (int g = base + tid; g < base + nf; g += 256) {
                float d = af[g] - ef[g];
                acc += c_W5[(unsigned)g % 5u] * d * d;
            }
            tot += acc * s_rrs;
        }
        {
            const int base = row0 * 3;
            const int nf   = rows * 3;
            const float* mf = (const float*)mu4;
            float acc = 0.f;
            for (int g = base + tid; g < base + nf; g += 256) {
                float d = mf[g] - MU_PRIOR;
                acc += d * d;
            }
            tot += acc * s_mu;
        }
        {
            const int base = row0 * 9;
            const int nf   = rows * 9;
            const float* pf = (const float*)pred4;
            const float* qf = (const float*)yobs4;
            const float* zf = (const float*)nan4;
            const float* cf = (const float*)cov4;
            for (int j = tid; j < nf; j += 256) {
                float d = pf[base + j] - qf[base + j];
                s_dy2[j] = d * d;
                float z = zf[base + j];
                s_fin[j] = (z == z) ? 1.f : 0.f;
                s_cov[j] = cf[base + j];
            }
        }
        __syncthreads();
        for (int r = tid; r < rows; r += 256) {
            const float* dy = &s_dy2[r * 9];
            const float* fi = &s_fin[r * 9];
            const float* cm = &s_cov[r * 9];
            float rsum = 0.f, lens = 0.f;
            #pragma unroll
            for (int i = 0; i < 9; i++) { rsum += dy[i]; lens += fi[i]; }
            tot += __fdividef(rsum, lens) * s_obs;
            float m0 = cm[0], m1 = cm[1], m2 = cm[2];
            float m3 = cm[3], m4 = cm[4], m5 = cm[5];
            float m6 = cm[6], m7 = cm[7], m8 = cm[8];
            float tr  = m0 + m4 + m8;
            float det = m0 * (m4 * m8 - m5 * m7)
                      - m1 * (m3 * m8 - m5 * m6)
                      + m2 * (m3 * m7 - m4 * m6);
            tot += ((LOGDET_SA - __logf(det)) + tr * INV49) * s_dk;
        }
    }

    // ---- params l2 (block 0 only) ----
    if (b == 0) {
        float acc = 0.f;
        for (int i = tid; i < np; i += 256) {
            float d = prm[i] - 1.f;
            acc += d * d;
        }
        tot += acc / (float)np;
    }

    // ---- block reduction + grid finalize ----
    #pragma unroll
    for (int o = 16; o > 0; o >>= 1) tot += __shfl_down_sync(0xffffffffu, tot, o);
    int lane = tid & 31;
    int wid  = tid >> 5;
    if (lane == 0) wsum[wid] = tot;
    __syncthreads();
    if (wid == 0) {
        float v = (lane < 8) ? wsum[lane] : 0.f;
        #pragma unroll
        for (int o = 4; o > 0; o >>= 1) v += __shfl_down_sync(0xffffffffu, v, o);
        if (lane == 0) {
            atomicAdd(&g_partial, v);
            __threadfence();
            unsigned c = atomicAdd(&g_count, 1u);
            if (c == (unsigned)(nblocks - 1)) {
                __threadfence();
                float total = atomicExch(&g_partial, 0.f);  // read + reset for replay
                out[0] = total;
                g_count = 0u;
            }
        }
    }
}

extern "C" void kernel_launch(void* const* d_in, const int* in_sizes, int n_in,
                              void* d_out, int out_size)
{
    const float4* pred = (const float4*)d_in[0];
    const float4* yobs = (const float4*)d_in[1];
    const float4* rrs  = (const float4*)d_in[2];
    const float4* rrsp = (const float4*)d_in[3];
    const float4* nana = (const float4*)d_in[4];
    const float4* cov  = (const float4*)d_in[5];
    const float4* mu   = (const float4*)d_in[6];
    const float*  prm  = (const float*)d_in[7];
    float* out = (float*)d_out;

    int n  = in_sizes[0] / 9;
    int np = in_sizes[7];
    int nblocks = (n + RPB - 1) / RPB;

    double dn = (double)n;
    float s_rrs = (float)(1.0 / (5.0 * dn));
    float s_obs = (float)(10.0 / dn);
    float s_dk  = (float)(0.5 / dn);
    float s_mu  = (float)(0.5 / (4.9 * 3.0 * dn));

    loss_kernel<<<nblocks, 256>>>(pred, yobs, rrs, rrsp, nana, cov, mu, prm,
                                  out, n, nblocks, np,
                                  s_rrs, s_obs, s_dk, s_mu);
}